// round 12
// baseline (speedup 1.0000x reference)
#include <cuda_runtime.h>
#include <cstdint>
#include <cstddef>

#define NN 50000
#define NE 600000
#define AS 100

#define INV_SQ96 0.10206207261596575f
#define INV_SQ12 0.2886751345948129f
#define INV_SQ32 0.17677669529663687f
#define INV_SC0  0.03125f
#define INV_SC1  0.04419417382415922f

__device__ __align__(16) float g_s1[NN * 64];
__device__ __align__(16) float g_v1[NN * 96];
__device__ __align__(16) float g_agg[NN * 160];
__device__ __align__(16) float g_f[NN * 192];

__device__ __forceinline__ float sigm_(float x) { return 1.f / (1.f + __expf(-x)); }
__device__ __forceinline__ float silu_(float x) { return x / (1.f + __expf(-x)); }
__device__ __forceinline__ void red4(float* p, float a, float b, float c, float d) {
    asm volatile("red.global.add.v4.f32 [%0], {%1,%2,%3,%4};"
                 :: "l"(p), "f"(a), "f"(b), "f"(c), "f"(d) : "memory");
}
__device__ __forceinline__ void ffma2_(unsigned long long& d, unsigned long long a, unsigned long long b) {
    asm("fma.rn.f32x2 %0, %1, %2, %0;" : "+l"(d) : "l"(a), "l"(b));
}
__device__ __forceinline__ float unpk_sum(unsigned long long v) {
    float lo, hi;
    asm("mov.b64 {%0,%1}, %2;" : "=f"(lo), "=f"(hi) : "l"(v));
    return lo + hi;
}

__global__ void k_zero() {
    size_t i = (size_t)blockIdx.x * blockDim.x + threadIdx.x;
    size_t n4 = (size_t)NN * 40;
    for (; i < n4; i += (size_t)gridDim.x * blockDim.x)
        ((float4*)g_agg)[i] = make_float4(0.f, 0.f, 0.f, 0.f);
}

// ---------------------------------------------------------------------------
// linear_1 as tiled GEMM: 128-node tiles, 512 threads
// ---------------------------------------------------------------------------
__global__ __launch_bounds__(512, 2) void k_premix2(const float* __restrict__ node_s,
                                                    const float* __restrict__ node_v,
                                                    const float* __restrict__ W1s,
                                                    const float* __restrict__ W1v) {
    extern __shared__ float sm[];
    float* sNs   = sm;           // 128*68
    float* sW1sT = sm + 8704;    // 64*68
    float* sNv   = sm + 13056;   // 384*36
    float* sW1vT = sm + 26880;   // 32*36  -> total 28032
    int t = threadIdx.x;
    int n0 = blockIdx.x * 128;
    for (int i = t; i < 128 * 64; i += 512) {
        int nl = i >> 6, u = i & 63; int n = n0 + nl;
        sNs[nl * 68 + u] = (n < NN) ? __ldg(node_s + (size_t)n * 64 + u) : 0.f;
    }
    for (int i = t; i < 64 * 64; i += 512) {
        int u = i >> 6, v = i & 63;
        sW1sT[v * 68 + u] = W1s[u * 64 + v];
    }
    for (int i = t; i < 384 * 32; i += 512) {
        int row = i >> 5, u = i & 31;
        int nl = row & 127, c = row >> 7; int n = n0 + nl;
        sNv[row * 36 + u] = (n < NN) ? __ldg(node_v + (size_t)n * 96 + u * 3 + c) : 0.f;
    }
    for (int i = t; i < 32 * 32; i += 512) {
        int u = i >> 5, v = i & 31;
        sW1vT[v * 36 + u] = W1v[u * 32 + v];
    }
    __syncthreads();

    {
        int rg = t >> 5, cg = t & 31;
        unsigned long long acc2[16];
        #pragma unroll
        for (int i = 0; i < 16; i++) acc2[i] = 0ull;
        #pragma unroll 4
        for (int k4 = 0; k4 < 16; k4++) {
            ulonglong2 a[8], b[2];
            #pragma unroll
            for (int i = 0; i < 8; i++) a[i] = *(const ulonglong2*)(sNs + (rg * 8 + i) * 68 + k4 * 4);
            #pragma unroll
            for (int j = 0; j < 2; j++) b[j] = *(const ulonglong2*)(sW1sT + (cg + 32 * j) * 68 + k4 * 4);
            #pragma unroll
            for (int i = 0; i < 8; i++)
                #pragma unroll
                for (int j = 0; j < 2; j++) {
                    ffma2_(acc2[i * 2 + j], a[i].x, b[j].x);
                    ffma2_(acc2[i * 2 + j], a[i].y, b[j].y);
                }
        }
        #pragma unroll
        for (int i = 0; i < 8; i++) {
            int n = n0 + rg * 8 + i;
            if (n < NN)
                #pragma unroll
                for (int j = 0; j < 2; j++)
                    g_s1[(size_t)n * 64 + cg + 32 * j] = unpk_sum(acc2[i * 2 + j]) * 0.125f;
        }
    }
    {
        int rg = t >> 3, cg = t & 7;
        unsigned long long acc2[24];
        #pragma unroll
        for (int i = 0; i < 24; i++) acc2[i] = 0ull;
        #pragma unroll 4
        for (int k4 = 0; k4 < 8; k4++) {
            ulonglong2 a[6], b[4];
            #pragma unroll
            for (int i = 0; i < 6; i++) a[i] = *(const ulonglong2*)(sNv + (rg * 6 + i) * 36 + k4 * 4);
            #pragma unroll
            for (int j = 0; j < 4; j++) b[j] = *(const ulonglong2*)(sW1vT + (cg + 8 * j) * 36 + k4 * 4);
            #pragma unroll
            for (int i = 0; i < 6; i++)
                #pragma unroll
                for (int j = 0; j < 4; j++) {
                    ffma2_(acc2[i * 4 + j], a[i].x, b[j].x);
                    ffma2_(acc2[i * 4 + j], a[i].y, b[j].y);
                }
        }
        #pragma unroll
        for (int i = 0; i < 6; i++) {
            int row = rg * 6 + i;
            int c = row >> 7, nl = row & 127;
            int n = n0 + nl;
            if (n < NN)
                #pragma unroll
                for (int j = 0; j < 4; j++)
                    g_v1[(size_t)n * 96 + (cg + 8 * j) * 3 + c] = unpk_sum(acc2[i * 4 + j]) * INV_SQ32;
        }
    }
}

// ---------------------------------------------------------------------------
// edge messages: 512 threads, 64-edge tiles, persistent
// ---------------------------------------------------------------------------
__global__ __launch_bounds__(512, 1) void k_edges(
    const float* __restrict__ edge_emb, const float* __restrict__ sh0,
    const float* __restrict__ sh1, const int* __restrict__ eidx,
    const float* __restrict__ Wm1, const float* __restrict__ Wm2,
    const float* __restrict__ W2s, const float* __restrict__ W2v) {
    extern __shared__ float sm[];
    float* sWm1 = sm;                 // 64
    float* sWm2 = sm + 64;            // 1536
    float* sW2sT = sm + 1600;         // 96*100
    float* sW2vT = sm + 11200;        // 32*100
    float* sTpS = sm + 14400;         // 64*100
    float* sTpV = sm + 20800;         // 192*100
    float* sGate = sm + 40000;        // 64*32
    int* sDst = (int*)(sm + 42048);   // 64
    int* sSrc = (int*)(sm + 42112);   // 64
    float* sEmb = sm + 42176;         // 64*8
    float* sW   = sm + 43200;         // 64*200 -> total 56000

    int t = threadIdx.x, warp = t >> 5, lane = t & 31;
    for (int i = t; i < 64; i += 512) sWm1[i] = Wm1[i];
    for (int i = t; i < 1536; i += 512) sWm2[i] = Wm2[i];
    for (int i = t; i < 96 * 96; i += 512) { int u = i / 96, j = i % 96; sW2sT[j * AS + u] = W2s[i]; }
    for (int i = t; i < 96 * 32; i += 512) { int u = i / 32, v = i % 32; sW2vT[v * AS + u] = W2v[i]; }
    // hoisted red-phase index math (divisions out of the hot loop)
    int veE[3], veG[3];
    #pragma unroll
    for (int r = 0; r < 3; r++) { int idx = t + 512 * r; veE[r] = idx / 24; veG[r] = idx % 24; }
    __syncthreads();

    for (int tile = blockIdx.x; tile < NE / 64; tile += gridDim.x) {
        int e0 = tile * 64;
        sEmb[t] = __ldg(edge_emb + (size_t)e0 * 8 + t);
        if (t < 64) sSrc[t] = __ldg(eidx + e0 + t);
        else if (t < 128) sDst[t - 64] = __ldg(eidx + NE + e0 + (t - 64));
        __syncthreads();
        // fused MLP: thread (e, c0) computes hidden itself, then 24 output cols
        {
            int e = t >> 3, c0 = t & 7;
            float h[8];
            #pragma unroll
            for (int k = 0; k < 8; k++) {
                float a = 0.f;
                #pragma unroll
                for (int r = 0; r < 8; r++) a = fmaf(sEmb[e * 8 + r], sWm1[r * 8 + k], a);
                h[k] = silu_(a);
            }
            #pragma unroll
            for (int q = 0; q < 24; q++) {
                int c = c0 + 8 * q;
                float a = 0.f;
                #pragma unroll
                for (int k = 0; k < 8; k++) a = fmaf(h[k], sWm2[k * 192 + c], a);
                sW[e * 200 + c] = a;
            }
        }
        __syncthreads();
        for (int sub = warp; sub < 64; sub += 16) {
            int e = e0 + sub;
            int src = sSrc[sub];
            const float* wrow = sW + sub * 200;
            float w0l = wrow[lane], w0h = wrow[32 + lane];
            float w1l = wrow[64 + lane], w1h = wrow[96 + lane];
            float w1b = wrow[128 + lane], w0b = wrow[160 + lane];
            float ss0 = g_s1[(size_t)src * 64 + lane];
            float ss1 = g_s1[(size_t)src * 64 + 32 + lane];
            float vx = g_v1[(size_t)src * 96 + lane * 3 + 0];
            float vy = g_v1[(size_t)src * 96 + lane * 3 + 1];
            float vz = g_v1[(size_t)src * 96 + lane * 3 + 2];
            float s0 = __ldg(sh0 + e);
            float e1x = __ldg(sh1 + (size_t)e * 3 + 0);
            float e1y = __ldg(sh1 + (size_t)e * 3 + 1);
            float e1z = __ldg(sh1 + (size_t)e * 3 + 2);
            float vdot = vx * e1x + vy * e1y + vz * e1z;
            sTpS[sub * AS + lane]      = w0l * ss0 * s0;
            sTpS[sub * AS + 32 + lane] = w0h * ss1 * s0;
            sTpS[sub * AS + 64 + lane] = w0b * vdot;
            float t1l = w1l * ss0, t1h = w1h * ss1, tb = w1b * s0;
            float* r0 = sTpV + (sub * 3 + 0) * AS;
            float* r1 = sTpV + (sub * 3 + 1) * AS;
            float* r2 = sTpV + (sub * 3 + 2) * AS;
            r0[lane] = t1l * e1x; r1[lane] = t1l * e1y; r2[lane] = t1l * e1z;
            r0[32 + lane] = t1h * e1x; r1[32 + lane] = t1h * e1y; r2[32 + lane] = t1h * e1z;
            r0[64 + lane] = tb * vx; r1[64 + lane] = tb * vy; r2[64 + lane] = tb * vz;
        }
        __syncthreads();

        unsigned long long acc2[24];
        #pragma unroll
        for (int i = 0; i < 24; i++) acc2[i] = 0ull;
        if (t < 256) {
            int rg = t >> 5, cg = t & 31;
            #pragma unroll 4
            for (int k4 = 0; k4 < 24; k4++) {
                ulonglong2 a[8], b[3];
                #pragma unroll
                for (int i = 0; i < 8; i++) a[i] = *(const ulonglong2*)(sTpS + (rg * 8 + i) * AS + k4 * 4);
                #pragma unroll
                for (int j = 0; j < 3; j++) b[j] = *(const ulonglong2*)(sW2sT + (cg + 32 * j) * AS + k4 * 4);
                #pragma unroll
                for (int i = 0; i < 8; i++)
                    #pragma unroll
                    for (int j = 0; j < 3; j++) {
                        ffma2_(acc2[i * 3 + j], a[i].x, b[j].x);
                        ffma2_(acc2[i * 3 + j], a[i].y, b[j].y);
                    }
            }
        } else {
            int t2 = t - 256;
            int rg = t2 >> 3, cg = t2 & 7;
            #pragma unroll 4
            for (int k4 = 0; k4 < 24; k4++) {
                ulonglong2 a[6], b[4];
                #pragma unroll
                for (int i = 0; i < 6; i++) a[i] = *(const ulonglong2*)(sTpV + (rg * 6 + i) * AS + k4 * 4);
                #pragma unroll
                for (int j = 0; j < 4; j++) b[j] = *(const ulonglong2*)(sW2vT + (cg + 8 * j) * AS + k4 * 4);
                #pragma unroll
                for (int i = 0; i < 6; i++)
                    #pragma unroll
                    for (int j = 0; j < 4; j++) {
                        ffma2_(acc2[i * 4 + j], a[i].x, b[j].x);
                        ffma2_(acc2[i * 4 + j], a[i].y, b[j].y);
                    }
            }
        }
        __syncthreads();

        if (t < 256) {
            int rg = t >> 5, cg = t & 31;
            #pragma unroll
            for (int i = 0; i < 8; i++) {
                int row = rg * 8 + i;
                #pragma unroll
                for (int j = 0; j < 3; j++) {
                    int col = cg + 32 * j;
                    float m = unpk_sum(acc2[i * 3 + j]) * INV_SQ96;
                    if (col < 64) sTpS[row * AS + col] = silu_(m) * INV_SQ12;
                    else          sGate[row * 32 + (col - 64)] = sigm_(m);
                }
            }
        } else {
            int t2 = t - 256;
            int rg = t2 >> 3, cg = t2 & 7;
            #pragma unroll
            for (int i = 0; i < 6; i++)
                #pragma unroll
                for (int j = 0; j < 4; j++)
                    sTpV[(rg * 6 + i) * AS + cg + 8 * j] = unpk_sum(acc2[i * 4 + j]) * INV_SQ96;
        }
        __syncthreads();

        #pragma unroll
        for (int r = 0; r < 2; r++) {
            int idx = t + 512 * r;
            int e = idx >> 4, g = idx & 15;
            const float* q = sTpS + e * AS + g * 4;
            red4(g_agg + (size_t)sDst[e] * 160 + g * 4, q[0], q[1], q[2], q[3]);
        }
        #pragma unroll
        for (int r = 0; r < 3; r++) {
            int e = veE[r], g = veG[r];
            float vals[4];
            #pragma unroll
            for (int qq = 0; qq < 4; qq++) {
                int f = g * 4 + qq; int v = f / 3, c = f - v * 3;
                vals[qq] = sTpV[(e * 3 + c) * AS + v] * sGate[e * 32 + v] * INV_SQ12;
            }
            red4(g_agg + (size_t)sDst[e] * 160 + 64 + g * 4, vals[0], vals[1], vals[2], vals[3]);
        }
        __syncthreads();
    }
}

// ---------------------------------------------------------------------------
// fused scalar update + self-connection scalars -> g_f[:, :96]
// 256 threads, 8x6 tile, register double-buffered B
// ---------------------------------------------------------------------------
__global__ __launch_bounds__(256, 1) void k_sc_s(const float* __restrict__ node_s,
                                                 const float* __restrict__ node_attrs,
                                                 const float* __restrict__ Wsc0,
                                                 const float* __restrict__ Wt0,
                                                 const float* __restrict__ W3s) {
    extern __shared__ float sm[];
    float* sS    = sm;           // 128*64
    float* sA    = sm + 8192;    // 128*16
    float* Ac    = sm + 10240;   // 128*132
    float* Bt    = sm + 27136;   // 96*132
    float* sWt0T = sm + 39808;   // 16*68
    float* sW3sT = sm + 40896;   // 96*68
    float* sU0   = sm + 47424;   // 128*68 -> total 56128
    int t = threadIdx.x;
    int n0 = blockIdx.x * 128;
    for (int i = t; i < 128 * 64; i += 256) { int n = n0 + (i >> 6); sS[i] = (n < NN) ? __ldg(node_s + (size_t)n * 64 + (i & 63)) : 0.f; }
    for (int i = t; i < 128 * 16; i += 256) { int n = n0 + (i >> 4); sA[i] = (n < NN) ? __ldg(node_attrs + (size_t)n * 16 + (i & 15)) : 0.f; }
    for (int i = t; i < 16 * 64; i += 256) { int a = i >> 6, u = i & 63; sWt0T[a * 68 + u] = Wt0[u * 16 + a]; }
    for (int i = t; i < 64 * 96; i += 256) { int u = i >> 6; int v = i - u * 96 + ((i & 63) >= 32 ? 0 : 0); v = i % 96; u = i / 96; sW3sT[v * 68 + u] = W3s[i] * 0.125f; }
    __syncthreads();
    for (int i = t; i < 128 * 64; i += 256) {
        int nl = i >> 6, u = i & 63; int n = n0 + nl;
        float w0 = 0.f;
        #pragma unroll
        for (int a = 0; a < 16; a++) w0 = fmaf(sA[nl * 16 + a], sWt0T[a * 68 + u], w0);
        sU0[nl * 68 + u] = (n < NN) ? g_agg[(size_t)n * 160 + u] * w0 * 0.25f : 0.f;
    }
    // prefetch first B chunk
    float4 breg[12];
    int bkk = t >> 1, bv0 = (t & 1) * 48;
    #pragma unroll
    for (int q = 0; q < 12; q++)
        breg[q] = __ldg((const float4*)(Wsc0 + (size_t)bkk * 96 + bv0 + 4 * q));

    int rg = t >> 4, cg = t & 15;
    unsigned long long acc2[48];
    #pragma unroll
    for (int i = 0; i < 48; i++) acc2[i] = 0ull;
    __syncthreads();
    // GEMM 1: u0 @ W3sT (K=64)
    #pragma unroll 4
    for (int k4 = 0; k4 < 16; k4++) {
        ulonglong2 a[8], b[6];
        #pragma unroll
        for (int i = 0; i < 8; i++) a[i] = *(const ulonglong2*)(sU0 + (rg * 8 + i) * 68 + k4 * 4);
        #pragma unroll
        for (int j = 0; j < 6; j++) b[j] = *(const ulonglong2*)(sW3sT + (cg + 16 * j) * 68 + k4 * 4);
        #pragma unroll
        for (int i = 0; i < 8; i++)
            #pragma unroll
            for (int j = 0; j < 6; j++) {
                ffma2_(acc2[i * 6 + j], a[i].x, b[j].x);
                ffma2_(acc2[i * 6 + j], a[i].y, b[j].y);
            }
    }
    // GEMM 2: (node_s x attrs) @ Wsc0 (K=1024, chunked, B double-buffered)
    for (int kc = 0; kc < 1024; kc += 128) {
        __syncthreads();
        #pragma unroll
        for (int q = 0; q < 12; q++) {
            Bt[(bv0 + 4 * q + 0) * 132 + bkk] = breg[q].x * INV_SC0;
            Bt[(bv0 + 4 * q + 1) * 132 + bkk] = breg[q].y * INV_SC0;
            Bt[(bv0 + 4 * q + 2) * 132 + bkk] = breg[q].z * INV_SC0;
            Bt[(bv0 + 4 * q + 3) * 132 + bkk] = breg[q].w * INV_SC0;
        }
        for (int i = t; i < 128 * 128; i += 256) {
            int n = i >> 7, kk = i & 127, k = kc + kk;
            Ac[n * 132 + kk] = sS[n * 64 + (k >> 4)] * sA[n * 16 + (k & 15)];
        }
        __syncthreads();
        if (kc < 896) {
            #pragma unroll
            for (int q = 0; q < 12; q++)
                breg[q] = __ldg((const float4*)(Wsc0 + (size_t)(kc + 128 + bkk) * 96 + bv0 + 4 * q));
        }
        #pragma unroll 4
        for (int k4 = 0; k4 < 32; k4++) {
            ulonglong2 a[8], b[6];
            #pragma unroll
            for (int i = 0; i < 8; i++) a[i] = *(const ulonglong2*)(Ac + (rg * 8 + i) * 132 + k4 * 4);
            #pragma unroll
            for (int j = 0; j < 6; j++) b[j] = *(const ulonglong2*)(Bt + (cg + 16 * j) * 132 + k4 * 4);
            #pragma unroll
            for (int i = 0; i < 8; i++)
                #pragma unroll
                for (int j = 0; j < 6; j++) {
                    ffma2_(acc2[i * 6 + j], a[i].x, b[j].x);
                    ffma2_(acc2[i * 6 + j], a[i].y, b[j].y);
                }
        }
    }
    #pragma unroll
    for (int i = 0; i < 8; i++) {
        int n = n0 + rg * 8 + i;
        if (n < NN)
            #pragma unroll
            for (int j = 0; j < 6; j++)
                g_f[(size_t)n * 192 + cg + 16 * j] = unpk_sum(acc2[i * 6 + j]);
    }
}

// ---------------------------------------------------------------------------
// fused vector update + self-connection vectors + gate + output
// 256 threads, 6x4 tile, register double-buffered B
// ---------------------------------------------------------------------------
__global__ __launch_bounds__(256, 1) void k_sc_v_out(const float* __restrict__ node_v,
                                                     const float* __restrict__ node_attrs,
                                                     const float* __restrict__ Wsc1,
                                                     const float* __restrict__ Wt1,
                                                     const float* __restrict__ W3v,
                                                     float* __restrict__ out) {
    extern __shared__ float sm[];
    float* sV    = sm;           // 64*96
    float* sA    = sm + 6144;    // 64*16
    float* Ac    = sm + 7168;    // 192*132
    float* Bt    = sm + 32512;   // 32*132
    float* sWt1T = sm + 36736;   // 16*36
    float* sW3vT = sm + 37312;   // 32*36
    float* sU1   = sm + 38464;   // 192*36 -> total 45376
    int t = threadIdx.x;
    int n0 = blockIdx.x * 64;
    for (int i = t; i < 64 * 96; i += 256) { int n = n0 + i / 96; sV[i] = (n < NN) ? __ldg(node_v + (size_t)n * 96 + i % 96) : 0.f; }
    for (int i = t; i < 64 * 16; i += 256) { int n = n0 + (i >> 4); sA[i] = (n < NN) ? __ldg(node_attrs + (size_t)n * 16 + (i & 15)) : 0.f; }
    for (int i = t; i < 16 * 32; i += 256) { int a = i >> 5, u = i & 31; sWt1T[a * 36 + u] = Wt1[u * 16 + a]; }
    for (int i = t; i < 32 * 32; i += 256) { int u = i >> 5, v = i & 31; sW3vT[v * 36 + u] = W3v[u * 32 + v] * INV_SQ32; }
    __syncthreads();
    for (int i = t; i < 192 * 32; i += 256) {
        int row = i >> 5, u = i & 31;
        int nl = row & 63, c = row >> 6;
        int n = n0 + nl;
        float w1 = 0.f;
        #pragma unroll
        for (int a = 0; a < 16; a++) w1 = fmaf(sA[nl * 16 + a], sWt1T[a * 36 + u], w1);
        sU1[row * 36 + u] = (n < NN) ? g_agg[(size_t)n * 160 + 64 + u * 3 + c] * w1 * 0.25f : 0.f;
    }
    // prefetch first B chunk (32 x 128 per chunk)
    float4 breg[4];
    int bkk = t >> 1, bw0 = (t & 1) * 16;
    #pragma unroll
    for (int q = 0; q < 4; q++)
        breg[q] = __ldg((const float4*)(Wsc1 + (size_t)bkk * 32 + bw0 + 4 * q));

    int rg = t >> 3, cg = t & 7;
    unsigned long long acc2[24];
    #pragma unroll
    for (int i = 0; i < 24; i++) acc2[i] = 0ull;
    __syncthreads();
    // GEMM 1: u1 @ W3vT (K=32)
    #pragma unroll 4
    for (int k4 = 0; k4 < 8; k4++) {
        ulonglong2 a[6], b[4];
        #pragma unroll
        for (int i = 0; i < 6; i++) a[i] = *(const ulonglong2*)(sU1 + (rg * 6 + i) * 36 + k4 * 4);
        #pragma unroll
        for (int j = 0; j < 4; j++) b[j] = *(const ulonglong2*)(sW3vT + (cg + 8 * j) * 36 + k4 * 4);
        #pragma unroll
        for (int i = 0; i < 6; i++)
            #pragma unroll
            for (int j = 0; j < 4; j++) {
                ffma2_(acc2[i * 4 + j], a[i].x, b[j].x);
                ffma2_(acc2[i * 4 + j], a[i].y, b[j].y);
            }
    }
    // GEMM 2: (node_v x attrs) @ Wsc1 (K=512, chunked, B double-buffered)
    for (int kc = 0; kc < 512; kc += 128) {
        __syncthreads();
        #pragma unroll
        for (int q = 0; q < 4; q++) {
            Bt[(bw0 + 4 * q + 0) * 132 + bkk] = breg[q].x * INV_SC1;
            Bt[(bw0 + 4 * q + 1) * 132 + bkk] = breg[q].y * INV_SC1;
            Bt[(bw0 + 4 * q + 2) * 132 + bkk] = breg[q].z * INV_SC1;
            Bt[(bw0 + 4 * q + 3) * 132 + bkk] = breg[q].w * INV_SC1;
        }
        for (int i = t; i < 192 * 128; i += 256) {
            int row = i >> 7, kk = i & 127, k = kc + kk;
            int c = row >> 6, nl = row & 63;
            Ac[row * 132 + kk] = sV[nl * 96 + (k >> 4) * 3 + c] * sA[nl * 16 + (k & 15)];
        }
        __syncthreads();
        if (kc < 384) {
            #pragma unroll
            for (int q = 0; q < 4; q++)
                breg[q] = __ldg((const float4*)(Wsc1 + (size_t)(kc + 128 + bkk) * 32 + bw0 + 4 * q));
        }
        #pragma unroll 4
        for (int k4 = 0; k4 < 32; k4++) {
            ulonglong2 a[6], b[4];
            #pragma unroll
            for (int i = 0; i < 6; i++) a[i] = *(const ulonglong2*)(Ac + (rg * 6 + i) * 132 + k4 * 4);
            #pragma unroll
            for (int j = 0; j < 4; j++) b[j] = *(const ulonglong2*)(Bt + (cg + 8 * j) * 132 + k4 * 4);
            #pragma unroll
            for (int i = 0; i < 6; i++)
                #pragma unroll
                for (int j = 0; j < 4; j++) {
                    ffma2_(acc2[i * 4 + j], a[i].x, b[j].x);
                    ffma2_(acc2[i * 4 + j], a[i].y, b[j].y);
                }
        }
    }
    #pragma unroll
    for (int i = 0; i < 6; i++) {
        int row = rg * 6 + i;
        int c = row >> 6, nl = row & 63;
        int n = n0 + nl;
        if (n < NN) {
            #pragma unroll
            for (int j = 0; j < 4; j++) {
                int v = cg + 8 * j;
                float fv = unpk_sum(acc2[i * 4 + j]);
                float gate = sigm_(g_f[(size_t)n * 192 + 64 + v]);
                out[(size_t)n * 160 + 64 + v * 3 + c] = fv * gate;
            }
        }
    }
    __syncthreads();
    for (int i = t; i < 64 * 64; i += 256) {
        int nl = i >> 6, v = i & 63;
        int n = n0 + nl;
        if (n < NN) out[(size_t)n * 160 + v] = silu_(g_f[(size_t)n * 192 + v]);
    }
}

extern "C" void kernel_launch(void* const* d_in, const int* in_sizes, int n_in,
                              void* d_out, int out_size) {
    const float* node_s     = (const float*)d_in[0];
    const float* node_v     = (const float*)d_in[1];
    const float* node_attrs = (const float*)d_in[2];
    const float* edge_emb   = (const float*)d_in[3];
    const float* edge_sh0   = (const float*)d_in[4];
    const float* edge_sh1   = (const float*)d_in[5];
    const int*   edge_index = (const int*)d_in[6];
    const float* W1s  = (const float*)d_in[7];
    const float* W1v  = (const float*)d_in[8];
    const float* Wm1  = (const float*)d_in[9];
    const float* Wm2  = (const float*)d_in[10];
    const float* W2s  = (const float*)d_in[11];
    const float* W2v  = (const float*)d_in[12];
    const float* Wt0  = (const float*)d_in[13];
    const float* Wt1  = (const float*)d_in[14];
    const float* W3s  = (const float*)d_in[15];
    const float* W3v  = (const float*)d_in[16];
    const float* Wsc0 = (const float*)d_in[17];
    const float* Wsc1 = (const float*)d_in[18];
    float* out = (float*)d_out;

    static bool attr_done = false;
    if (!attr_done) {
        cudaFuncSetAttribute(k_premix2, cudaFuncAttributeMaxDynamicSharedMemorySize, 28032 * 4);
        cudaFuncSetAttribute(k_edges, cudaFuncAttributeMaxDynamicSharedMemorySize, 56000 * 4);
        cudaFuncSetAttribute(k_sc_s, cudaFuncAttributeMaxDynamicSharedMemorySize, 56128 * 4);
        cudaFuncSetAttribute(k_sc_v_out, cudaFuncAttributeMaxDynamicSharedMemorySize, 45376 * 4);
        attr_done = true;
    }

    k_zero<<<2048, 256>>>();
    k_premix2<<<(NN + 127) / 128, 512, 28032 * 4>>>(node_s, node_v, W1s, W1v);
    k_edges<<<148, 512, 56000 * 4>>>(edge_emb, edge_sh0, edge_sh1, edge_index,
                                     Wm1, Wm2, W2s, W2v);
    k_sc_s<<<(NN + 127) / 128, 256, 56128 * 4>>>(node_s, node_attrs, Wsc0, Wt0, W3s);
    k_sc_v_out<<<(NN + 63) / 64, 256, 45376 * 4>>>(node_v, node_attrs, Wsc1, Wt1, W3v, out);
}

// round 15
// speedup vs baseline: 1.0691x; 1.0691x over previous
#include <cuda_runtime.h>
#include <cstdint>
#include <cstddef>

#define NN 50000
#define NE 600000
#define AS 100

#define INV_SQ96 0.10206207261596575f
#define INV_SQ12 0.2886751345948129f
#define INV_SQ32 0.17677669529663687f
#define INV_SC0  0.03125f
#define INV_SC1  0.04419417382415922f

__device__ __align__(16) float g_s1[NN * 64];
__device__ __align__(16) float g_v1[NN * 96];
__device__ __align__(16) float g_agg[NN * 160];
__device__ __align__(16) float g_f[NN * 192];

__device__ __forceinline__ float sigm_(float x) { return 1.f / (1.f + __expf(-x)); }
__device__ __forceinline__ float silu_(float x) { return x / (1.f + __expf(-x)); }
__device__ __forceinline__ void red4(float* p, float a, float b, float c, float d) {
    asm volatile("red.global.add.v4.f32 [%0], {%1,%2,%3,%4};"
                 :: "l"(p), "f"(a), "f"(b), "f"(c), "f"(d) : "memory");
}
__device__ __forceinline__ void ffma2_(unsigned long long& d, unsigned long long a, unsigned long long b) {
    asm("fma.rn.f32x2 %0, %1, %2, %0;" : "+l"(d) : "l"(a), "l"(b));
}
__device__ __forceinline__ float unpk_sum(unsigned long long v) {
    float lo, hi;
    asm("mov.b64 {%0,%1}, %2;" : "=f"(lo), "=f"(hi) : "l"(v));
    return lo + hi;
}

__global__ void k_zero() {
    size_t i = (size_t)blockIdx.x * blockDim.x + threadIdx.x;
    size_t n4 = (size_t)NN * 40;
    for (; i < n4; i += (size_t)gridDim.x * blockDim.x)
        ((float4*)g_agg)[i] = make_float4(0.f, 0.f, 0.f, 0.f);
}

// ---------------------------------------------------------------------------
// linear_1 as tiled GEMM: 128-node tiles, 512 threads  (unchanged from best)
// ---------------------------------------------------------------------------
__global__ __launch_bounds__(512, 2) void k_premix2(const float* __restrict__ node_s,
                                                    const float* __restrict__ node_v,
                                                    const float* __restrict__ W1s,
                                                    const float* __restrict__ W1v) {
    extern __shared__ float sm[];
    float* sNs   = sm;           // 128*68
    float* sW1sT = sm + 8704;    // 64*68
    float* sNv   = sm + 13056;   // 384*36
    float* sW1vT = sm + 26880;   // 32*36  -> total 28032
    int t = threadIdx.x;
    int n0 = blockIdx.x * 128;
    for (int i = t; i < 128 * 64; i += 512) {
        int nl = i >> 6, u = i & 63; int n = n0 + nl;
        sNs[nl * 68 + u] = (n < NN) ? __ldg(node_s + (size_t)n * 64 + u) : 0.f;
    }
    for (int i = t; i < 64 * 64; i += 512) {
        int u = i >> 6, v = i & 63;
        sW1sT[v * 68 + u] = W1s[u * 64 + v];
    }
    for (int i = t; i < 384 * 32; i += 512) {
        int row = i >> 5, u = i & 31;
        int nl = row & 127, c = row >> 7; int n = n0 + nl;
        sNv[row * 36 + u] = (n < NN) ? __ldg(node_v + (size_t)n * 96 + u * 3 + c) : 0.f;
    }
    for (int i = t; i < 32 * 32; i += 512) {
        int u = i >> 5, v = i & 31;
        sW1vT[v * 36 + u] = W1v[u * 32 + v];
    }
    __syncthreads();

    {
        int rg = t >> 5, cg = t & 31;
        unsigned long long acc2[16];
        #pragma unroll
        for (int i = 0; i < 16; i++) acc2[i] = 0ull;
        #pragma unroll 4
        for (int k4 = 0; k4 < 16; k4++) {
            ulonglong2 a[8], b[2];
            #pragma unroll
            for (int i = 0; i < 8; i++) a[i] = *(const ulonglong2*)(sNs + (rg * 8 + i) * 68 + k4 * 4);
            #pragma unroll
            for (int j = 0; j < 2; j++) b[j] = *(const ulonglong2*)(sW1sT + (cg + 32 * j) * 68 + k4 * 4);
            #pragma unroll
            for (int i = 0; i < 8; i++)
                #pragma unroll
                for (int j = 0; j < 2; j++) {
                    ffma2_(acc2[i * 2 + j], a[i].x, b[j].x);
                    ffma2_(acc2[i * 2 + j], a[i].y, b[j].y);
                }
        }
        #pragma unroll
        for (int i = 0; i < 8; i++) {
            int n = n0 + rg * 8 + i;
            if (n < NN)
                #pragma unroll
                for (int j = 0; j < 2; j++)
                    g_s1[(size_t)n * 64 + cg + 32 * j] = unpk_sum(acc2[i * 2 + j]) * 0.125f;
        }
    }
    {
        int rg = t >> 3, cg = t & 7;
        unsigned long long acc2[24];
        #pragma unroll
        for (int i = 0; i < 24; i++) acc2[i] = 0ull;
        #pragma unroll 4
        for (int k4 = 0; k4 < 8; k4++) {
            ulonglong2 a[6], b[4];
            #pragma unroll
            for (int i = 0; i < 6; i++) a[i] = *(const ulonglong2*)(sNv + (rg * 6 + i) * 36 + k4 * 4);
            #pragma unroll
            for (int j = 0; j < 4; j++) b[j] = *(const ulonglong2*)(sW1vT + (cg + 8 * j) * 36 + k4 * 4);
            #pragma unroll
            for (int i = 0; i < 6; i++)
                #pragma unroll
                for (int j = 0; j < 4; j++) {
                    ffma2_(acc2[i * 4 + j], a[i].x, b[j].x);
                    ffma2_(acc2[i * 4 + j], a[i].y, b[j].y);
                }
        }
        #pragma unroll
        for (int i = 0; i < 6; i++) {
            int row = rg * 6 + i;
            int c = row >> 7, nl = row & 127;
            int n = n0 + nl;
            if (n < NN)
                #pragma unroll
                for (int j = 0; j < 4; j++)
                    g_v1[(size_t)n * 96 + (cg + 8 * j) * 3 + c] = unpk_sum(acc2[i * 4 + j]) * INV_SQ32;
        }
    }
}

// ---------------------------------------------------------------------------
// edge messages: 512 threads, 64-edge tiles, persistent (known-best version)
// ---------------------------------------------------------------------------
__global__ __launch_bounds__(512, 1) void k_edges(
    const float* __restrict__ edge_emb, const float* __restrict__ sh0,
    const float* __restrict__ sh1, const int* __restrict__ eidx,
    const float* __restrict__ Wm1, const float* __restrict__ Wm2,
    const float* __restrict__ W2s, const float* __restrict__ W2v) {
    extern __shared__ float sm[];
    float* sWm1 = sm;                 // 64
    float* sWm2 = sm + 64;            // 1536
    float* sW2sT = sm + 1600;         // 96*100
    float* sW2vT = sm + 11200;        // 32*100
    float* sTpS = sm + 14400;         // 64*100
    float* sTpV = sm + 20800;         // 192*100
    float* sGate = sm + 40000;        // 64*32
    int* sDst = (int*)(sm + 42048);   // 64
    int* sSrc = (int*)(sm + 42112);   // 64
    float* sEmb = sm + 42176;         // 64*8
    float* sHid = sm + 42688;         // 64*8
    float* sW   = sm + 43200;         // 64*200 -> total 56000

    int t = threadIdx.x, warp = t >> 5, lane = t & 31;
    for (int i = t; i < 64; i += 512) sWm1[i] = Wm1[i];
    for (int i = t; i < 1536; i += 512) sWm2[i] = Wm2[i];
    for (int i = t; i < 96 * 96; i += 512) { int u = i / 96, j = i % 96; sW2sT[j * AS + u] = W2s[i]; }
    for (int i = t; i < 96 * 32; i += 512) { int u = i / 32, v = i % 32; sW2vT[v * AS + u] = W2v[i]; }
    __syncthreads();

    for (int tile = blockIdx.x; tile < NE / 64; tile += gridDim.x) {
        int e0 = tile * 64;
        sEmb[t] = __ldg(edge_emb + (size_t)e0 * 8 + t);
        if (t < 64) sSrc[t] = __ldg(eidx + e0 + t);
        else if (t < 128) sDst[t - 64] = __ldg(eidx + NE + e0 + (t - 64));
        __syncthreads();
        {
            int e = t >> 3, k = t & 7;
            float a = 0.f;
            #pragma unroll
            for (int r = 0; r < 8; r++) a = fmaf(sEmb[e * 8 + r], sWm1[r * 8 + k], a);
            sHid[t] = silu_(a);
        }
        __syncthreads();
        {
            int e = t >> 3, c0 = t & 7;
            float h[8];
            #pragma unroll
            for (int k = 0; k < 8; k++) h[k] = sHid[e * 8 + k];
            #pragma unroll
            for (int q = 0; q < 24; q++) {
                int c = c0 + 8 * q;
                float a = 0.f;
                #pragma unroll
                for (int k = 0; k < 8; k++) a = fmaf(h[k], sWm2[k * 192 + c], a);
                sW[e * 200 + c] = a;
            }
        }
        __syncthreads();
        for (int sub = warp; sub < 64; sub += 16) {
            int e = e0 + sub;
            int src = sSrc[sub];
            const float* wrow = sW + sub * 200;
            float w0l = wrow[lane], w0h = wrow[32 + lane];
            float w1l = wrow[64 + lane], w1h = wrow[96 + lane];
            float w1b = wrow[128 + lane], w0b = wrow[160 + lane];
            float ss0 = g_s1[(size_t)src * 64 + lane];
            float ss1 = g_s1[(size_t)src * 64 + 32 + lane];
            float vx = g_v1[(size_t)src * 96 + lane * 3 + 0];
            float vy = g_v1[(size_t)src * 96 + lane * 3 + 1];
            float vz = g_v1[(size_t)src * 96 + lane * 3 + 2];
            float s0 = __ldg(sh0 + e);
            float e1x = __ldg(sh1 + (size_t)e * 3 + 0);
            float e1y = __ldg(sh1 + (size_t)e * 3 + 1);
            float e1z = __ldg(sh1 + (size_t)e * 3 + 2);
            float vdot = vx * e1x + vy * e1y + vz * e1z;
            sTpS[sub * AS + lane]      = w0l * ss0 * s0;
            sTpS[sub * AS + 32 + lane] = w0h * ss1 * s0;
            sTpS[sub * AS + 64 + lane] = w0b * vdot;
            float t1l = w1l * ss0, t1h = w1h * ss1, tb = w1b * s0;
            float* r0 = sTpV + (sub * 3 + 0) * AS;
            float* r1 = sTpV + (sub * 3 + 1) * AS;
            float* r2 = sTpV + (sub * 3 + 2) * AS;
            r0[lane] = t1l * e1x; r1[lane] = t1l * e1y; r2[lane] = t1l * e1z;
            r0[32 + lane] = t1h * e1x; r1[32 + lane] = t1h * e1y; r2[32 + lane] = t1h * e1z;
            r0[64 + lane] = tb * vx; r1[64 + lane] = tb * vy; r2[64 + lane] = tb * vz;
        }
        __syncthreads();

        unsigned long long acc2[24];
        #pragma unroll
        for (int i = 0; i < 24; i++) acc2[i] = 0ull;
        if (t < 256) {
            int rg = t >> 5, cg = t & 31;
            #pragma unroll 4
            for (int k4 = 0; k4 < 24; k4++) {
                ulonglong2 a[8], b[3];
                #pragma unroll
                for (int i = 0; i < 8; i++) a[i] = *(const ulonglong2*)(sTpS + (rg * 8 + i) * AS + k4 * 4);
                #pragma unroll
                for (int j = 0; j < 3; j++) b[j] = *(const ulonglong2*)(sW2sT + (cg + 32 * j) * AS + k4 * 4);
                #pragma unroll
                for (int i = 0; i < 8; i++)
                    #pragma unroll
                    for (int j = 0; j < 3; j++) {
                        ffma2_(acc2[i * 3 + j], a[i].x, b[j].x);
                        ffma2_(acc2[i * 3 + j], a[i].y, b[j].y);
                    }
            }
        } else {
            int t2 = t - 256;
            int rg = t2 >> 3, cg = t2 & 7;
            #pragma unroll 4
            for (int k4 = 0; k4 < 24; k4++) {
                ulonglong2 a[6], b[4];
                #pragma unroll
                for (int i = 0; i < 6; i++) a[i] = *(const ulonglong2*)(sTpV + (rg * 6 + i) * AS + k4 * 4);
                #pragma unroll
                for (int j = 0; j < 4; j++) b[j] = *(const ulonglong2*)(sW2vT + (cg + 8 * j) * AS + k4 * 4);
                #pragma unroll
                for (int i = 0; i < 6; i++)
                    #pragma unroll
                    for (int j = 0; j < 4; j++) {
                        ffma2_(acc2[i * 4 + j], a[i].x, b[j].x);
                        ffma2_(acc2[i * 4 + j], a[i].y, b[j].y);
                    }
            }
        }
        __syncthreads();

        if (t < 256) {
            int rg = t >> 5, cg = t & 31;
            #pragma unroll
            for (int i = 0; i < 8; i++) {
                int row = rg * 8 + i;
                #pragma unroll
                for (int j = 0; j < 3; j++) {
                    int col = cg + 32 * j;
                    float m = unpk_sum(acc2[i * 3 + j]) * INV_SQ96;
                    if (col < 64) sTpS[row * AS + col] = silu_(m) * INV_SQ12;
                    else          sGate[row * 32 + (col - 64)] = sigm_(m);
                }
            }
        } else {
            int t2 = t - 256;
            int rg = t2 >> 3, cg = t2 & 7;
            #pragma unroll
            for (int i = 0; i < 6; i++)
                #pragma unroll
                for (int j = 0; j < 4; j++)
                    sTpV[(rg * 6 + i) * AS + cg + 8 * j] = unpk_sum(acc2[i * 4 + j]) * INV_SQ96;
        }
        __syncthreads();

        #pragma unroll
        for (int r = 0; r < 2; r++) {
            int idx = t + 512 * r;
            int e = idx >> 4, g = idx & 15;
            const float* q = sTpS + e * AS + g * 4;
            red4(g_agg + (size_t)sDst[e] * 160 + g * 4, q[0], q[1], q[2], q[3]);
        }
        #pragma unroll
        for (int r = 0; r < 3; r++) {
            int idx = t + 512 * r;
            int e = idx / 24, g = idx % 24;
            float vals[4];
            #pragma unroll
            for (int qq = 0; qq < 4; qq++) {
                int f = g * 4 + qq; int v = f / 3, c = f - v * 3;
                vals[qq] = sTpV[(e * 3 + c) * AS + v] * sGate[e * 32 + v] * INV_SQ12;
            }
            red4(g_agg + (size_t)sDst[e] * 160 + 64 + g * 4, vals[0], vals[1], vals[2], vals[3]);
        }
        __syncthreads();
    }
}

// ---------------------------------------------------------------------------
// fused scalar update + self-connection scalars -> g_f[:, :96]
// 256 threads, 64-node tile, K=64 chunks, 2 CTAs/SM
// ---------------------------------------------------------------------------
__global__ __launch_bounds__(256, 2) void k_sc_s(const float* __restrict__ node_s,
                                                 const float* __restrict__ node_attrs,
                                                 const float* __restrict__ Wsc0,
                                                 const float* __restrict__ Wt0,
                                                 const float* __restrict__ W3s) {
    extern __shared__ float sm[];
    float* sS    = sm;           // 64*64   = 4096
    float* sA    = sm + 4096;    // 64*16   = 1024
    float* Ac    = sm + 5120;    // 64*68   = 4352
    float* Bt    = sm + 9472;    // 96*68   = 6528
    float* sWt0T = sm + 16000;   // 16*68   = 1088
    float* sW3sT = sm + 17088;   // 96*68   = 6528
    float* sU0   = sm + 23616;   // 64*68   = 4352 -> total 27968 (111872 B)
    int t = threadIdx.x;
    int n0 = blockIdx.x * 64;
    for (int i = t; i < 64 * 64; i += 256) { int n = n0 + (i >> 6); sS[i] = (n < NN) ? __ldg(node_s + (size_t)n * 64 + (i & 63)) : 0.f; }
    for (int i = t; i < 64 * 16; i += 256) { int n = n0 + (i >> 4); sA[i] = (n < NN) ? __ldg(node_attrs + (size_t)n * 16 + (i & 15)) : 0.f; }
    for (int i = t; i < 16 * 64; i += 256) { int a = i >> 6, u = i & 63; sWt0T[a * 68 + u] = Wt0[u * 16 + a]; }
    for (int i = t; i < 64 * 96; i += 256) { int u = i / 96, v = i % 96; sW3sT[v * 68 + u] = W3s[i] * 0.125f; }
    __syncthreads();
    for (int i = t; i < 64 * 64; i += 256) {
        int nl = i >> 6, u = i & 63; int n = n0 + nl;
        float w0 = 0.f;
        #pragma unroll
        for (int a = 0; a < 16; a++) w0 = fmaf(sA[nl * 16 + a], sWt0T[a * 68 + u], w0);
        sU0[nl * 68 + u] = (n < NN) ? g_agg[(size_t)n * 160 + u] * w0 * 0.25f : 0.f;
    }
    // B prefetch mapping: 6 float4/thread per chunk (chunk = 64 kk x 96 v)
    int kkq[6], v4q[6];
    #pragma unroll
    for (int q = 0; q < 6; q++) { int i4 = q * 256 + t; kkq[q] = i4 / 24; v4q[q] = i4 % 24; }
    float4 breg[6];
    #pragma unroll
    for (int q = 0; q < 6; q++)
        breg[q] = __ldg((const float4*)(Wsc0 + (size_t)kkq[q] * 96 + v4q[q] * 4));

    int rg = t >> 5, cg = t & 31;
    unsigned long long acc2[24];
    #pragma unroll
    for (int i = 0; i < 24; i++) acc2[i] = 0ull;
    __syncthreads();
    // GEMM 1: u0 @ W3sT (K=64)
    #pragma unroll 4
    for (int k4 = 0; k4 < 16; k4++) {
        ulonglong2 a[8], b[3];
        #pragma unroll
        for (int i = 0; i < 8; i++) a[i] = *(const ulonglong2*)(sU0 + (rg * 8 + i) * 68 + k4 * 4);
        #pragma unroll
        for (int j = 0; j < 3; j++) b[j] = *(const ulonglong2*)(sW3sT + (cg + 32 * j) * 68 + k4 * 4);
        #pragma unroll
        for (int i = 0; i < 8; i++)
            #pragma unroll
            for (int j = 0; j < 3; j++) {
                ffma2_(acc2[i * 3 + j], a[i].x, b[j].x);
                ffma2_(acc2[i * 3 + j], a[i].y, b[j].y);
            }
    }
    // GEMM 2: (node_s x attrs) @ Wsc0, K=1024 in 16 chunks of 64
    for (int kc = 0; kc < 1024; kc += 64) {
        __syncthreads();
        #pragma unroll
        for (int q = 0; q < 6; q++) {
            float* bp = Bt + v4q[q] * 4 * 68 + kkq[q];
            bp[0]       = breg[q].x * INV_SC0;
            bp[68]      = breg[q].y * INV_SC0;
            bp[136]     = breg[q].z * INV_SC0;
            bp[204]     = breg[q].w * INV_SC0;
        }
        for (int i = t; i < 64 * 64; i += 256) {
            int n = i >> 6, kk = i & 63, k = kc + kk;
            Ac[n * 68 + kk] = sS[n * 64 + (k >> 4)] * sA[n * 16 + (k & 15)];
        }
        __syncthreads();
        if (kc < 960) {
            #pragma unroll
            for (int q = 0; q < 6; q++)
                breg[q] = __ldg((const float4*)(Wsc0 + (size_t)(kc + 64 + kkq[q]) * 96 + v4q[q] * 4));
        }
        #pragma unroll 4
        for (int k4 = 0; k4 < 16; k4++) {
            ulonglong2 a[8], b[3];
            #pragma unroll
            for (int i = 0; i < 8; i++) a[i] = *(const ulonglong2*)(Ac + (rg * 8 + i) * 68 + k4 * 4);
            #pragma unroll
            for (int j = 0; j < 3; j++) b[j] = *(const ulonglong2*)(Bt + (cg + 32 * j) * 68 + k4 * 4);
            #pragma unroll
            for (int i = 0; i < 8; i++)
                #pragma unroll
                for (int j = 0; j < 3; j++) {
                    ffma2_(acc2[i * 3 + j], a[i].x, b[j].x);
                    ffma2_(acc2[i * 3 + j], a[i].y, b[j].y);
                }
        }
    }
    #pragma unroll
    for (int i = 0; i < 8; i++) {
        int n = n0 + rg * 8 + i;
        if (n < NN)
            #pragma unroll
            for (int j = 0; j < 3; j++)
                g_f[(size_t)n * 192 + cg + 32 * j] = unpk_sum(acc2[i * 3 + j]);
    }
}

// ---------------------------------------------------------------------------
// fused vector update + self-connection vectors + gate + output
// 256 threads, 32-node tile, K=64 chunks, 3 CTAs/SM
// ---------------------------------------------------------------------------
__global__ __launch_bounds__(256, 3) void k_sc_v_out(const float* __restrict__ node_v,
                                                     const float* __restrict__ node_attrs,
                                                     const float* __restrict__ Wsc1,
                                                     const float* __restrict__ Wt1,
                                                     const float* __restrict__ W3v,
                                                     float* __restrict__ out) {
    extern __shared__ float sm[];
    float* sV    = sm;           // 32*96  = 3072
    float* sA    = sm + 3072;    // 32*16  = 512
    float* Ac    = sm + 3584;    // 96*68  = 6528
    float* Bt    = sm + 10112;   // 32*68  = 2176
    float* sWt1T = sm + 12288;   // 16*36  = 576
    float* sW3vT = sm + 12864;   // 32*36  = 1152
    float* sU1   = sm + 14016;   // 96*36  = 3456 -> total 17472 (69888 B)
    int t = threadIdx.x;
    int n0 = blockIdx.x * 32;
    for (int i = t; i < 32 * 96; i += 256) { int n = n0 + i / 96; sV[i] = (n < NN) ? __ldg(node_v + (size_t)n * 96 + i % 96) : 0.f; }
    for (int i = t; i < 32 * 16; i += 256) { int n = n0 + (i >> 4); sA[i] = (n < NN) ? __ldg(node_attrs + (size_t)n * 16 + (i & 15)) : 0.f; }
    for (int i = t; i < 16 * 32; i += 256) { int a = i >> 5, u = i & 31; sWt1T[a * 36 + u] = Wt1[u * 16 + a]; }
    for (int i = t; i < 32 * 32; i += 256) { int u = i >> 5, v = i & 31; sW3vT[v * 36 + u] = W3v[u * 32 + v] * INV_SQ32; }
    __syncthreads();
    for (int i = t; i < 96 * 32; i += 256) {
        int row = i >> 5, u = i & 31;
        int nl = row & 31, c = row >> 5;
        int n = n0 + nl;
        float w1 = 0.f;
        #pragma unroll
        for (int a = 0; a < 16; a++) w1 = fmaf(sA[nl * 16 + a], sWt1T[a * 36 + u], w1);
        sU1[row * 36 + u] = (n < NN) ? g_agg[(size_t)n * 160 + 64 + u * 3 + c] * w1 * 0.25f : 0.f;
    }
    // B prefetch: chunk = 64 kk x 32 w = 512 float4; 2 per thread
    int kkq[2], w4q[2];
    #pragma unroll
    for (int q = 0; q < 2; q++) { int i4 = q * 256 + t; kkq[q] = i4 >> 3; w4q[q] = i4 & 7; }
    float4 breg[2];
    #pragma unroll
    for (int q = 0; q < 2; q++)
        breg[q] = __ldg((const float4*)(Wsc1 + (size_t)kkq[q] * 32 + w4q[q] * 4));

    int rg = t >> 4, cg = t & 15;
    unsigned long long acc2[12];
    #pragma unroll
    for (int i = 0; i < 12; i++) acc2[i] = 0ull;
    __syncthreads();
    // GEMM 1: u1 @ W3vT (K=32)
    #pragma unroll 4
    for (int k4 = 0; k4 < 8; k4++) {
        ulonglong2 a[6], b[2];
        #pragma unroll
        for (int i = 0; i < 6; i++) a[i] = *(const ulonglong2*)(sU1 + (rg * 6 + i) * 36 + k4 * 4);
        #pragma unroll
        for (int j = 0; j < 2; j++) b[j] = *(const ulonglong2*)(sW3vT + (cg + 16 * j) * 36 + k4 * 4);
        #pragma unroll
        for (int i = 0; i < 6; i++)
            #pragma unroll
            for (int j = 0; j < 2; j++) {
                ffma2_(acc2[i * 2 + j], a[i].x, b[j].x);
                ffma2_(acc2[i * 2 + j], a[i].y, b[j].y);
            }
    }
    // GEMM 2: (node_v x attrs) @ Wsc1, K=512 in 8 chunks of 64
    for (int kc = 0; kc < 512; kc += 64) {
        __syncthreads();
        #pragma unroll
        for (int q = 0; q < 2; q++) {
            float* bp = Bt + w4q[q] * 4 * 68 + kkq[q];
            bp[0]   = breg[q].x * INV_SC1;
            bp[68]  = breg[q].y * INV_SC1;
            bp[136] = breg[q].z * INV_SC1;
            bp[204] = breg[q].w * INV_SC1;
        }
        for (int i = t; i < 96 * 64; i += 256) {
            int row = i >> 6, kk = i & 63, k = kc + kk;
            int c = row >> 5, nl = row & 31;
            Ac[row * 68 + kk] = sV[nl * 96 + (k >> 4) * 3 + c] * sA[nl * 16 + (k & 15)];
        }
        __syncthreads();
        if (kc < 448) {
            #pragma unroll
            for (int q = 0; q < 2; q++)
                breg[q] = __ldg((const float4*)(Wsc1 + (size_t)(kc + 64 + kkq[q]) * 32 + w4q[q] * 4));
        }
        #pragma unroll 4
        for (int k4 = 0; k4 < 16; k4++) {
            ulonglong2 a[6], b[2];
            #pragma unroll
            for (int i = 0; i < 6; i++) a[i] = *(const ulonglong2*)(Ac + (rg * 6 + i) * 68 + k4 * 4);
            #pragma unroll
            for (int j = 0; j < 2; j++) b[j] = *(const ulonglong2*)(Bt + (cg + 16 * j) * 68 + k4 * 4);
            #pragma unroll
            for (int i = 0; i < 6; i++)
                #pragma unroll
                for (int j = 0; j < 2; j++) {
                    ffma2_(acc2[i * 2 + j], a[i].x, b[j].x);
                    ffma2_(acc2[i * 2 + j], a[i].y, b[j].y);
                }
        }
    }
    #pragma unroll
    for (int i = 0; i < 6; i++) {
        int row = rg * 6 + i;
        int c = row >> 5, nl = row & 31;
        int n = n0 + nl;
        if (n < NN) {
            #pragma unroll
            for (int j = 0; j < 2; j++) {
                int v = cg + 16 * j;
                float fv = unpk_sum(acc2[i * 2 + j]);
                float gate = sigm_(g_f[(size_t)n * 192 + 64 + v]);
                out[(size_t)n * 160 + 64 + v * 3 + c] = fv * gate;
            }
        }
    }
    __syncthreads();
    for (int i = t; i < 32 * 64; i += 256) {
        int nl = i >> 6, v = i & 63;
        int n = n0 + nl;
        if (n < NN) out[(size_t)n * 160 + v] = silu_(g_f[(size_t)n * 192 + v]);
    }
}

extern "C" void kernel_launch(void* const* d_in, const int* in_sizes, int n_in,
                              void* d_out, int out_size) {
    const float* node_s     = (const float*)d_in[0];
    const float* node_v     = (const float*)d_in[1];
    const float* node_attrs = (const float*)d_in[2];
    const float* edge_emb   = (const float*)d_in[3];
    const float* edge_sh0   = (const float*)d_in[4];
    const float* edge_sh1   = (const float*)d_in[5];
    const int*   edge_index = (const int*)d_in[6];
    const float* W1s  = (const float*)d_in[7];
    const float* W1v  = (const float*)d_in[8];
    const float* Wm1  = (const float*)d_in[9];
    const float* Wm2  = (const float*)d_in[10];
    const float* W2s  = (const float*)d_in[11];
    const float* W2v  = (const float*)d_in[12];
    const float* Wt0  = (const float*)d_in[13];
    const float* Wt1  = (const float*)d_in[14];
    const float* W3s  = (const float*)d_in[15];
    const float* W3v  = (const float*)d_in[16];
    const float* Wsc0 = (const float*)d_in[17];
    const float* Wsc1 = (const float*)d_in[18];
    float* out = (float*)d_out;

    static bool attr_done = false;
    if (!attr_done) {
        cudaFuncSetAttribute(k_premix2, cudaFuncAttributeMaxDynamicSharedMemorySize, 28032 * 4);
        cudaFuncSetAttribute(k_edges, cudaFuncAttributeMaxDynamicSharedMemorySize, 56000 * 4);
        cudaFuncSetAttribute(k_sc_s, cudaFuncAttributeMaxDynamicSharedMemorySize, 27968 * 4);
        cudaFuncSetAttribute(k_sc_v_out, cudaFuncAttributeMaxDynamicSharedMemorySize, 17472 * 4);
        attr_done = true;
    }

    k_zero<<<2048, 256>>>();
    k_premix2<<<(NN + 127) / 128, 512, 28032 * 4>>>(node_s, node_v, W1s, W1v);
    k_edges<<<148, 512, 56000 * 4>>>(edge_emb, edge_sh0, edge_sh1, edge_index,
                                     Wm1, Wm2, W2s, W2v);
    k_sc_s<<<(NN + 63) / 64, 256, 27968 * 4>>>(node_s, node_attrs, Wsc0, Wt0, W3s);
    k_sc_v_out<<<(NN + 31) / 32, 256, 17472 * 4>>>(node_v, node_attrs, Wsc1, Wt1, W3v, out);
}